// round 2
// baseline (speedup 1.0000x reference)
#include <cuda_runtime.h>
#include <cuda_bf16.h>
#include <float.h>
#include <stdint.h>

// Problem constants (fixed by the reference: x[32,2048,512], codebook[1024,512])
#define C_DIM   512
#define K_CODES 1024
#define MAX_ROWS 65536

// GEMM tile config
#define BM 128
#define BN 128
#define BK 16
#define TM 8
#define TN 8
#define NTHREADS 256

// Device scratch (no allocations allowed in kernel_launch)
__device__ float g_cnorm[K_CODES];
__device__ float g_xnorm[MAX_ROWS];
__device__ int   g_idx[MAX_ROWS];
__device__ float g_partial[MAX_ROWS];

// ---------------------------------------------------------------------------
// Warp row-norm: XLA-style. Thread t accumulates elements t, t+32, ... with a
// sequential FMA chain, then shfl_down tree (16,8,4,2,1). Lane 0 has result.
// ---------------------------------------------------------------------------
__device__ __forceinline__ float warp_rownorm(const float* __restrict__ row, int lane) {
    float s = 0.f;
    #pragma unroll
    for (int i = 0; i < C_DIM / 32; i++) {
        float v = row[lane + 32 * i];
        s = fmaf(v, v, s);
    }
    s += __shfl_down_sync(0xFFFFFFFFu, s, 16);
    s += __shfl_down_sync(0xFFFFFFFFu, s, 8);
    s += __shfl_down_sync(0xFFFFFFFFu, s, 4);
    s += __shfl_down_sync(0xFFFFFFFFu, s, 2);
    s += __shfl_down_sync(0xFFFFFFFFu, s, 1);
    return s;
}

// Kernel 0a: codebook squared norms (one code per warp).
__global__ __launch_bounds__(256) void cnorm_kernel(const float* __restrict__ cb) {
    int code = blockIdx.x * 8 + (threadIdx.x >> 5);
    int lane = threadIdx.x & 31;
    float s = warp_rownorm(cb + (size_t)code * C_DIM, lane);
    if (lane == 0) g_cnorm[code] = s;
}

// Kernel 0b: x row squared norms (one row per warp).
__global__ __launch_bounds__(256) void xnorm_kernel(const float* __restrict__ x) {
    int row = blockIdx.x * 8 + (threadIdx.x >> 5);
    int lane = threadIdx.x & 31;
    float s = warp_rownorm(x + (size_t)row * C_DIM, lane);
    if (lane == 0) g_xnorm[row] = s;
}

// ---------------------------------------------------------------------------
// Kernel 1: fused GEMM + argmin.
// Each CTA: 128 rows x all 1024 codes, 8 code tiles of 128.
// Score uses the reference's exact expression and rounding sequence:
//   d = fl( fl(Sx - fl(2*dot)) + Sc )
// so near-tie quantization matches jnp's fp32 distance; ties break to the
// lowest code index, matching argmax(-distance).
// ---------------------------------------------------------------------------
__global__ __launch_bounds__(NTHREADS, 2) void argmin_kernel(
    const float* __restrict__ x, const float* __restrict__ cb)
{
    __shared__ float As[BK][BM];      // x tile, k-major
    __shared__ float Bs[BK][BN];      // codebook tile, k-major
    __shared__ float cns[K_CODES];
    __shared__ float xns[BM];
    __shared__ float rv[BM][16];
    __shared__ int   ri[BM][16];

    const int tid = threadIdx.x;
    const int tx = tid & 15;          // code-tile column group
    const int ty = tid >> 4;          // row group
    const int rowBase = blockIdx.x * BM;

    for (int i = tid; i < K_CODES; i += NTHREADS) cns[i] = g_cnorm[i];
    if (tid < BM) xns[tid] = g_xnorm[rowBase + tid];

    float sx[TM];
    float bestv[TM];
    int   besti[TM];
    #pragma unroll
    for (int i = 0; i < TM; i++) { bestv[i] = FLT_MAX; besti[i] = 0; }

    // global-load mapping: 512 float4 per operand tile, 2 per thread
    const int r0 = (tid      ) >> 2, kq0 = ((tid      ) & 3) * 4;
    const int r1 = (tid + 256) >> 2, kq1 = ((tid + 256) & 3) * 4;

    for (int nt = 0; nt < K_CODES / BN; nt++) {
        float acc[TM][TN];
        #pragma unroll
        for (int i = 0; i < TM; i++)
            #pragma unroll
            for (int j = 0; j < TN; j++) acc[i][j] = 0.f;

        const float* cbt = cb + (size_t)(nt * BN) * C_DIM;

        for (int k0 = 0; k0 < C_DIM; k0 += BK) {
            __syncthreads();
            {
                float4 v = *(const float4*)(x + (size_t)(rowBase + r0) * C_DIM + k0 + kq0);
                As[kq0 + 0][r0] = v.x; As[kq0 + 1][r0] = v.y;
                As[kq0 + 2][r0] = v.z; As[kq0 + 3][r0] = v.w;
                float4 w = *(const float4*)(cbt + (size_t)r0 * C_DIM + k0 + kq0);
                Bs[kq0 + 0][r0] = w.x; Bs[kq0 + 1][r0] = w.y;
                Bs[kq0 + 2][r0] = w.z; Bs[kq0 + 3][r0] = w.w;
            }
            {
                float4 v = *(const float4*)(x + (size_t)(rowBase + r1) * C_DIM + k0 + kq1);
                As[kq1 + 0][r1] = v.x; As[kq1 + 1][r1] = v.y;
                As[kq1 + 2][r1] = v.z; As[kq1 + 3][r1] = v.w;
                float4 w = *(const float4*)(cbt + (size_t)r1 * C_DIM + k0 + kq1);
                Bs[kq1 + 0][r1] = w.x; Bs[kq1 + 1][r1] = w.y;
                Bs[kq1 + 2][r1] = w.z; Bs[kq1 + 3][r1] = w.w;
            }
            __syncthreads();

            #pragma unroll
            for (int k = 0; k < BK; k++) {
                float a_[TM], b_[TN];
                *(float4*)&a_[0] = *(const float4*)&As[k][ty * TM];
                *(float4*)&a_[4] = *(const float4*)&As[k][ty * TM + 4];
                *(float4*)&b_[0] = *(const float4*)&Bs[k][tx * TN];
                *(float4*)&b_[4] = *(const float4*)&Bs[k][tx * TN + 4];
                #pragma unroll
                for (int i = 0; i < TM; i++)
                    #pragma unroll
                    for (int j = 0; j < TN; j++)
                        acc[i][j] = fmaf(a_[i], b_[j], acc[i][j]);
            }
        }

        if (nt == 0) {
            #pragma unroll
            for (int i = 0; i < TM; i++) sx[i] = xns[ty * TM + i];
        }

        // epilogue: reference-identical rounding sequence.
        #pragma unroll
        for (int j = 0; j < TN; j++) {
            int code = nt * BN + tx * TN + j;
            float cn = cns[code];
            #pragma unroll
            for (int i = 0; i < TM; i++) {
                float t1 = __fmul_rn(2.0f, acc[i][j]);
                float t2 = __fsub_rn(sx[i], t1);
                float d  = __fadd_rn(t2, cn);
                if (d < bestv[i]) { bestv[i] = d; besti[i] = code; }
            }
        }
    }

    __syncthreads();
    #pragma unroll
    for (int i = 0; i < TM; i++) {
        rv[ty * TM + i][tx] = bestv[i];
        ri[ty * TM + i][tx] = besti[i];
    }
    __syncthreads();

    if (tid < BM) {
        float bv = rv[tid][0];
        int   bi = ri[tid][0];
        #pragma unroll
        for (int j = 1; j < 16; j++) {
            float v = rv[tid][j];
            int   id = ri[tid][j];
            if (v < bv || (v == bv && id < bi)) { bv = v; bi = id; }
        }
        g_idx[rowBase + tid] = bi;
    }
}

// ---------------------------------------------------------------------------
// Kernel 2: gather codebook rows into output + per-row squared-error partial.
// ---------------------------------------------------------------------------
__global__ __launch_bounds__(128) void gather_kernel(
    const float* __restrict__ x, const float* __restrict__ cb,
    float* __restrict__ out)
{
    int row = blockIdx.x;
    int t = threadIdx.x;
    int code = g_idx[row];

    const float4* xr = (const float4*)(x  + (size_t)row  * C_DIM);
    const float4* cr = (const float4*)(cb + (size_t)code * C_DIM);
    float4*       orr = (float4*)(out + (size_t)row * C_DIM);

    float4 xv = xr[t];
    float4 cv = cr[t];
    orr[t] = cv;

    float dx = xv.x - cv.x, dy = xv.y - cv.y, dz = xv.z - cv.z, dw = xv.w - cv.w;
    float s = dx * dx + dy * dy + dz * dz + dw * dw;

    #pragma unroll
    for (int o = 16; o > 0; o >>= 1) s += __shfl_xor_sync(0xFFFFFFFFu, s, o);

    __shared__ float ws[4];
    if ((t & 31) == 0) ws[t >> 5] = s;
    __syncthreads();
    if (t == 0) g_partial[row] = (ws[0] + ws[1]) + (ws[2] + ws[3]);
}

// ---------------------------------------------------------------------------
// Kernel 3: deterministic reduction of per-row partials -> commit loss.
// ---------------------------------------------------------------------------
__global__ __launch_bounds__(1024) void loss_kernel(
    float* __restrict__ out, int rows, long long out_size)
{
    int t = threadIdx.x;
    double s = 0.0;
    for (int i = t; i < rows; i += 1024) s += (double)g_partial[i];

    #pragma unroll
    for (int o = 16; o > 0; o >>= 1) s += __shfl_down_sync(0xFFFFFFFFu, s, o);

    __shared__ double ws[32];
    if ((t & 31) == 0) ws[t >> 5] = s;
    __syncthreads();
    if (t < 32) {
        double v = ws[t];
        #pragma unroll
        for (int o = 16; o > 0; o >>= 1) v += __shfl_down_sync(0xFFFFFFFFu, v, o);
        if (t == 0) {
            float loss = (float)(v / ((double)rows * (double)C_DIM));
            long long base = (long long)rows * C_DIM;
            for (long long i = base; i < out_size; i++) out[i] = loss;
        }
    }
}

// ---------------------------------------------------------------------------
extern "C" void kernel_launch(void* const* d_in, const int* in_sizes, int n_in,
                              void* d_out, int out_size)
{
    const float* x  = (const float*)d_in[0];
    const float* cb = (const float*)d_in[1];
    float* out = (float*)d_out;

    int rows = in_sizes[0] / C_DIM;   // 65536

    cnorm_kernel<<<K_CODES / 8, 256>>>(cb);
    xnorm_kernel<<<rows / 8, 256>>>(x);
    argmin_kernel<<<rows / BM, NTHREADS>>>(x, cb);
    gather_kernel<<<rows, 128>>>(x, cb, out);
    loss_kernel<<<1, 1024>>>(out, rows, (long long)out_size);
}